// round 3
// baseline (speedup 1.0000x reference)
#include <cuda_runtime.h>
#include <cuda_bf16.h>
#include <cstdint>

// ---------------------------------------------------------------------------
// NNUE forward, TF32-faithful.
//   transpose:   Ww/Wb (256 x 40960) -> WwT/WbT (40960 x 256), tf32-rounded
//   feat kernel: sparse-scan white/black multihot -> coalesced gather-sum of
//                transposed rows -> pov select -> relu -> base[B,512];
//                fused value head (512->32->32->1).
//   gemm NT:     hidden = relu(base @ Wm0^T + bm0)   [B,256]
//                a      = relu(hidden @ Wm1^T + bm1) [B,4096]
// ---------------------------------------------------------------------------

#define HALF_KP 40960
#define MOVE_N  4096
#define BATCH_MAX 4096

__device__ float g_WwT[(size_t)HALF_KP * 256];   // 42 MB
__device__ float g_WbT[(size_t)HALF_KP * 256];   // 42 MB
__device__ float g_base[BATCH_MAX * 512];
__device__ float g_hidden[BATCH_MAX * 256];

__device__ __forceinline__ float tf32r(float x) {
    uint32_t u;
    asm("cvt.rna.tf32.f32 %0, %1;" : "=r"(u) : "f"(x));
    return __uint_as_float(u);
}

// ---------------------------------------------------------------------------
// Transpose [256, HALF_KP] -> [HALF_KP, 256], tf32-rounding fused.
// 32x32 tiles, 32x8 threads.
// ---------------------------------------------------------------------------
__global__ __launch_bounds__(256) void transpose_kernel(
    const float* __restrict__ src, float* __restrict__ dst)
{
    __shared__ float tile[32][33];
    const int f0 = blockIdx.x * 32;
    const int o0 = blockIdx.y * 32;
    const int tx = threadIdx.x;      // 0..31
    const int ty = threadIdx.y;      // 0..7
    #pragma unroll
    for (int i = 0; i < 32; i += 8)
        tile[ty + i][tx] = tf32r(src[(size_t)(o0 + ty + i) * HALF_KP + f0 + tx]);
    __syncthreads();
    #pragma unroll
    for (int i = 0; i < 32; i += 8)
        dst[(size_t)(f0 + ty + i) * 256 + o0 + tx] = tile[tx][ty + i];
}

// ---------------------------------------------------------------------------
// Kernel A: feature extraction + value head. One block per position.
// ---------------------------------------------------------------------------
__global__ __launch_bounds__(256) void feat_kernel(
    const float* __restrict__ pov,
    const float* __restrict__ white,
    const float* __restrict__ black,
    const float* __restrict__ WwT, const float* __restrict__ bw,
    const float* __restrict__ WbT, const float* __restrict__ bb,
    const float* __restrict__ W0, const float* __restrict__ b0,
    const float* __restrict__ W1, const float* __restrict__ b1,
    const float* __restrict__ W2, const float* __restrict__ b2,
    float* __restrict__ xout)
{
    const int b = blockIdx.x;
    const int t = threadIdx.x;   // 256 threads

    __shared__ int   idxW[64], idxB[64];
    __shared__ int   cntW, cntB;
    __shared__ float sbase[512];
    __shared__ float h0[32], h1[32];

    if (t == 0) { cntW = 0; cntB = 0; }
    __syncthreads();

    // --- scan both multihot rows (exact 0.0/1.0 values) ---
    const float4* wrow = (const float4*)(white + (size_t)b * HALF_KP);
    const float4* brow = (const float4*)(black + (size_t)b * HALF_KP);
    #pragma unroll 4
    for (int i = t; i < HALF_KP / 4; i += 256) {
        float4 v = wrow[i];
        if (v.x != 0.f) { int p = atomicAdd(&cntW, 1); if (p < 64) idxW[p] = 4*i+0; }
        if (v.y != 0.f) { int p = atomicAdd(&cntW, 1); if (p < 64) idxW[p] = 4*i+1; }
        if (v.z != 0.f) { int p = atomicAdd(&cntW, 1); if (p < 64) idxW[p] = 4*i+2; }
        if (v.w != 0.f) { int p = atomicAdd(&cntW, 1); if (p < 64) idxW[p] = 4*i+3; }
        float4 u = brow[i];
        if (u.x != 0.f) { int p = atomicAdd(&cntB, 1); if (p < 64) idxB[p] = 4*i+0; }
        if (u.y != 0.f) { int p = atomicAdd(&cntB, 1); if (p < 64) idxB[p] = 4*i+1; }
        if (u.z != 0.f) { int p = atomicAdd(&cntB, 1); if (p < 64) idxB[p] = 4*i+2; }
        if (u.w != 0.f) { int p = atomicAdd(&cntB, 1); if (p < 64) idxB[p] = 4*i+3; }
    }
    __syncthreads();

    const int nW = min(cntW, 64);
    const int nB = min(cntB, 64);

    // --- coalesced gather-sum from transposed tables; thread t = column t ---
    float accw = 0.f;
    for (int i = 0; i < nW; i++)
        accw += WwT[(size_t)idxW[i] * 256 + t];
    accw += bw[t];
    float accb = 0.f;
    for (int i = 0; i < nB; i++)
        accb += WbT[(size_t)idxB[i] * 256 + t];
    accb += bb[t];

    // --- pov select + relu -> base ---
    const bool p = (pov[b] != 0.f);
    const float first  = p ? accw : accb;
    const float second = p ? accb : accw;
    const float r0 = fmaxf(first, 0.f);
    const float r1 = fmaxf(second, 0.f);
    sbase[t]       = r0;
    sbase[t + 256] = r1;
    float* baserow = g_base + (size_t)b * 512;
    baserow[t]       = r0;
    baserow[t + 256] = r1;
    __syncthreads();

    // --- value head (tiny; 32 threads), TF32-faithful ---
    if (t < 32) {
        float s = 0.f;
        const float* w = W0 + t * 512;
        #pragma unroll 8
        for (int k = 0; k < 512; k++) s += tf32r(w[k]) * tf32r(sbase[k]);
        h0[t] = fmaxf(s + b0[t], 0.f);
    }
    __syncthreads();
    if (t < 32) {
        float s = 0.f;
        const float* w = W1 + t * 32;
        #pragma unroll
        for (int k = 0; k < 32; k++) s += tf32r(w[k]) * tf32r(h0[k]);
        h1[t] = fmaxf(s + b1[t], 0.f);
    }
    __syncthreads();
    if (t == 0) {
        float s = 0.f;
        #pragma unroll
        for (int k = 0; k < 32; k++) s += tf32r(W2[k]) * tf32r(h1[k]);
        xout[b] = s + b2[0];
    }
}

// ---------------------------------------------------------------------------
// Tiled NT GEMM, TF32-faithful: C = relu?(A @ Bm^T + bias)
// Operands tf32-rounded at smem store; fp32 FFMA accumulate.
// BM=128 BN=64 BK=16, 256 threads, 8x4 microtile. Dims divisible.
// ---------------------------------------------------------------------------
template <bool RELU>
__global__ __launch_bounds__(256) void gemm_nt(
    const float* __restrict__ A,
    const float* __restrict__ Bm,
    const float* __restrict__ bias,
    float* __restrict__ C,
    int M, int N, int K)
{
    constexpr int BM = 128, BN = 64, BK = 16, TM = 8, TN = 4;
    __shared__ float As[BK][BM];
    __shared__ float Bs[BK][BN];

    const int tid = threadIdx.x;
    const int tx  = tid % (BN / TN);   // 0..15
    const int ty  = tid / (BN / TN);   // 0..15
    const int m0  = blockIdx.y * BM;
    const int n0  = blockIdx.x * BN;

    float acc[TM][TN];
    #pragma unroll
    for (int i = 0; i < TM; i++)
        #pragma unroll
        for (int j = 0; j < TN; j++) acc[i][j] = 0.f;

    constexpr int AF4 = BM * BK / 4;   // 512 float4 loads

    for (int k0 = 0; k0 < K; k0 += BK) {
        #pragma unroll
        for (int i = tid; i < AF4; i += 256) {
            int r  = i / (BK / 4);
            int c4 = i % (BK / 4);
            float4 v = *(const float4*)(A + (size_t)(m0 + r) * K + k0 + c4 * 4);
            As[c4*4+0][r] = tf32r(v.x); As[c4*4+1][r] = tf32r(v.y);
            As[c4*4+2][r] = tf32r(v.z); As[c4*4+3][r] = tf32r(v.w);
        }
        {
            int i  = tid;   // BN*BK/4 == 256 == blockDim
            int r  = i / (BK / 4);
            int c4 = i % (BK / 4);
            float4 v = *(const float4*)(Bm + (size_t)(n0 + r) * K + k0 + c4 * 4);
            Bs[c4*4+0][r] = tf32r(v.x); Bs[c4*4+1][r] = tf32r(v.y);
            Bs[c4*4+2][r] = tf32r(v.z); Bs[c4*4+3][r] = tf32r(v.w);
        }
        __syncthreads();

        #pragma unroll
        for (int k = 0; k < BK; k++) {
            float ra[TM], rb[TN];
            #pragma unroll
            for (int i = 0; i < TM; i++) ra[i] = As[k][ty * TM + i];
            #pragma unroll
            for (int j = 0; j < TN; j++) rb[j] = Bs[k][tx * TN + j];
            #pragma unroll
            for (int i = 0; i < TM; i++)
                #pragma unroll
                for (int j = 0; j < TN; j++)
                    acc[i][j] += ra[i] * rb[j];
        }
        __syncthreads();
    }

    #pragma unroll
    for (int i = 0; i < TM; i++) {
        const size_t row = (size_t)(m0 + ty * TM + i) * N + n0 + tx * TN;
        #pragma unroll
        for (int j = 0; j < TN; j++) {
            float v = acc[i][j] + bias[n0 + tx * TN + j];
            if (RELU) v = fmaxf(v, 0.f);
            C[row + j] = v;
        }
    }
}

// ---------------------------------------------------------------------------
extern "C" void kernel_launch(void* const* d_in, const int* in_sizes, int n_in,
                              void* d_out, int out_size)
{
    const float* pov   = (const float*)d_in[0];
    const float* white = (const float*)d_in[1];
    const float* black = (const float*)d_in[2];
    const float* Ww    = (const float*)d_in[3];
    const float* bw    = (const float*)d_in[4];
    const float* Wb    = (const float*)d_in[5];
    const float* bb    = (const float*)d_in[6];
    const float* W0    = (const float*)d_in[7];
    const float* b0    = (const float*)d_in[8];
    const float* W1    = (const float*)d_in[9];
    const float* b1    = (const float*)d_in[10];
    const float* W2    = (const float*)d_in[11];
    const float* b2    = (const float*)d_in[12];
    const float* Wm0   = (const float*)d_in[13];
    const float* bm0   = (const float*)d_in[14];
    const float* Wm1   = (const float*)d_in[15];
    const float* bm1   = (const float*)d_in[16];

    const int B = in_sizes[0];          // pov is [B,1]
    float* out  = (float*)d_out;
    float* xout = out;                  // [B]
    float* aout = out + B;              // [B, MOVE_N]

    float* wwT_ptr = nullptr; float* wbT_ptr = nullptr;
    float* base_ptr = nullptr; float* hidden_ptr = nullptr;
    cudaGetSymbolAddress((void**)&wwT_ptr,   g_WwT);
    cudaGetSymbolAddress((void**)&wbT_ptr,   g_WbT);
    cudaGetSymbolAddress((void**)&base_ptr,  g_base);
    cudaGetSymbolAddress((void**)&hidden_ptr, g_hidden);

    // Transpose feature tables (256 x HALF_KP -> HALF_KP x 256), tf32-rounded
    {
        dim3 grid(HALF_KP / 32, 256 / 32);
        dim3 blk(32, 8);
        transpose_kernel<<<grid, blk>>>(Ww, wwT_ptr);
        transpose_kernel<<<grid, blk>>>(Wb, wbT_ptr);
    }

    // Kernel A: features + value head
    feat_kernel<<<B, 256>>>(pov, white, black, wwT_ptr, bw, wbT_ptr, bb,
                            W0, b0, W1, b1, W2, b2, xout);

    // Kernel B: hidden = relu(base @ Wm0^T + bm0)   M=B, N=256, K=512
    {
        dim3 grid(256 / 64, B / 128);
        gemm_nt<true><<<grid, 256>>>(base_ptr, Wm0, bm0, hidden_ptr, B, 256, 512);
    }
    // Kernel C: a = relu(hidden @ Wm1^T + bm1)      M=B, N=4096, K=256
    {
        dim3 grid(MOVE_N / 64, B / 128);
        gemm_nt<true><<<grid, 256>>>(hidden_ptr, Wm1, bm1, aout, B, MOVE_N, 256);
    }
}

// round 5
// speedup vs baseline: 1.2768x; 1.2768x over previous
#include <cuda_runtime.h>
#include <cstdint>

// ---------------------------------------------------------------------------
// NNUE forward, TF32-faithful, target sm_100 (no tcgen05; mma.sync tensor ops)
//   transpose: Ww/Wb (256 x 40960) -> (40960 x 256), tf32-rounded
//   round:     Wm0/Wm1 -> tf32-rounded scratch
//   feat:      sparse-scan multihot -> gather-sum -> pov select -> relu ->
//              tf32-rounded base[B,512]; fused value head (512->32->32->1)
//   gemm_mma:  mma.sync m16n8k8 tf32, 128x128 CTA tile, cp.async 2-stage
//              hidden = tf32r(relu(base @ Wm0^T + bm0))   [B,256]
//              a      = relu(hidden @ Wm1^T + bm1)        [B,4096]
// ---------------------------------------------------------------------------

#define HALF_KP 40960
#define MOVE_N  4096
#define BATCH_MAX 4096

__device__ float g_WwT[(size_t)HALF_KP * 256];
__device__ float g_WbT[(size_t)HALF_KP * 256];
__device__ float g_base[BATCH_MAX * 512];
__device__ float g_hidden[BATCH_MAX * 256];
__device__ float g_Wm0r[256 * 512];
__device__ float g_Wm1r[(size_t)MOVE_N * 256];

__device__ __forceinline__ float tf32r(float x) {
    uint32_t u;
    asm("cvt.rna.tf32.f32 %0, %1;" : "=r"(u) : "f"(x));
    return __uint_as_float(u);
}

__device__ __forceinline__ uint32_t smem_to_u32(const void* p) {
    uint32_t a;
    asm("{ .reg .u64 t; cvta.to.shared.u64 t, %1; cvt.u32.u64 %0, t; }"
        : "=r"(a) : "l"(p));
    return a;
}

__device__ __forceinline__ void cp16(uint32_t dst, const void* src) {
    asm volatile("cp.async.cg.shared.global [%0], [%1], 16;"
                 :: "r"(dst), "l"(src) : "memory");
}

// ---------------------------------------------------------------------------
__global__ __launch_bounds__(256) void transpose_kernel(
    const float* __restrict__ src, float* __restrict__ dst)
{
    __shared__ float tile[32][33];
    const int f0 = blockIdx.x * 32;
    const int o0 = blockIdx.y * 32;
    const int tx = threadIdx.x;
    const int ty = threadIdx.y;
    #pragma unroll
    for (int i = 0; i < 32; i += 8)
        tile[ty + i][tx] = tf32r(src[(size_t)(o0 + ty + i) * HALF_KP + f0 + tx]);
    __syncthreads();
    #pragma unroll
    for (int i = 0; i < 32; i += 8)
        dst[(size_t)(f0 + ty + i) * 256 + o0 + tx] = tile[tx][ty + i];
}

__global__ __launch_bounds__(256) void round_kernel(
    const float* __restrict__ src, float* __restrict__ dst, int n4)
{
    int i = blockIdx.x * 256 + threadIdx.x;
    if (i < n4) {
        float4 v = ((const float4*)src)[i];
        float4 w;
        w.x = tf32r(v.x); w.y = tf32r(v.y); w.z = tf32r(v.z); w.w = tf32r(v.w);
        ((float4*)dst)[i] = w;
    }
}

// ---------------------------------------------------------------------------
// Feature extraction + value head. One block per position.
// ---------------------------------------------------------------------------
__global__ __launch_bounds__(256) void feat_kernel(
    const float* __restrict__ pov,
    const float* __restrict__ white,
    const float* __restrict__ black,
    const float* __restrict__ WwT, const float* __restrict__ bw,
    const float* __restrict__ WbT, const float* __restrict__ bb,
    const float* __restrict__ W0, const float* __restrict__ b0,
    const float* __restrict__ W1, const float* __restrict__ b1,
    const float* __restrict__ W2, const float* __restrict__ b2,
    float* __restrict__ xout)
{
    const int b = blockIdx.x;
    const int t = threadIdx.x;

    __shared__ int   idxW[64], idxB[64];
    __shared__ int   cntW, cntB;
    __shared__ float sbase[512];
    __shared__ float h0[32], h1[32];

    if (t == 0) { cntW = 0; cntB = 0; }
    __syncthreads();

    const float4* wrow = (const float4*)(white + (size_t)b * HALF_KP);
    const float4* brow = (const float4*)(black + (size_t)b * HALF_KP);
    #pragma unroll 4
    for (int i = t; i < HALF_KP / 4; i += 256) {
        float4 v = wrow[i];
        if (v.x != 0.f) { int p = atomicAdd(&cntW, 1); if (p < 64) idxW[p] = 4*i+0; }
        if (v.y != 0.f) { int p = atomicAdd(&cntW, 1); if (p < 64) idxW[p] = 4*i+1; }
        if (v.z != 0.f) { int p = atomicAdd(&cntW, 1); if (p < 64) idxW[p] = 4*i+2; }
        if (v.w != 0.f) { int p = atomicAdd(&cntW, 1); if (p < 64) idxW[p] = 4*i+3; }
        float4 u = brow[i];
        if (u.x != 0.f) { int p = atomicAdd(&cntB, 1); if (p < 64) idxB[p] = 4*i+0; }
        if (u.y != 0.f) { int p = atomicAdd(&cntB, 1); if (p < 64) idxB[p] = 4*i+1; }
        if (u.z != 0.f) { int p = atomicAdd(&cntB, 1); if (p < 64) idxB[p] = 4*i+2; }
        if (u.w != 0.f) { int p = atomicAdd(&cntB, 1); if (p < 64) idxB[p] = 4*i+3; }
    }
    __syncthreads();

    const int nW = min(cntW, 64);
    const int nB = min(cntB, 64);

    float accw = 0.f;
    for (int i = 0; i < nW; i++) accw += WwT[(size_t)idxW[i] * 256 + t];
    accw += bw[t];
    float accb = 0.f;
    for (int i = 0; i < nB; i++) accb += WbT[(size_t)idxB[i] * 256 + t];
    accb += bb[t];

    const bool p = (pov[b] != 0.f);
    // store tf32-rounded base (GEMM-B consumes it; value head re-rounds -> idempotent)
    const float r0 = tf32r(fmaxf(p ? accw : accb, 0.f));
    const float r1 = tf32r(fmaxf(p ? accb : accw, 0.f));
    sbase[t]       = r0;
    sbase[t + 256] = r1;
    float* baserow = g_base + (size_t)b * 512;
    baserow[t]       = r0;
    baserow[t + 256] = r1;
    __syncthreads();

    if (t < 32) {
        float s = 0.f;
        const float* w = W0 + t * 512;
        #pragma unroll 8
        for (int k = 0; k < 512; k++) s += tf32r(w[k]) * sbase[k];
        h0[t] = fmaxf(s + b0[t], 0.f);
    }
    __syncthreads();
    if (t < 32) {
        float s = 0.f;
        const float* w = W1 + t * 32;
        #pragma unroll
        for (int k = 0; k < 32; k++) s += tf32r(w[k]) * tf32r(h0[k]);
        h1[t] = fmaxf(s + b1[t], 0.f);
    }
    __syncthreads();
    if (t == 0) {
        float s = 0.f;
        #pragma unroll
        for (int k = 0; k < 32; k++) s += tf32r(W2[k]) * tf32r(h1[k]);
        xout[b] = s + b2[0];
    }
}

// ---------------------------------------------------------------------------
// TF32 mma.sync NT GEMM: C[M,N] = relu(A[M,K] @ Bm[N,K]^T + bias[N])
// A, Bm already tf32-rounded in gmem. 128x128 CTA tile, 8 warps, warp 64x32.
// K-chunk 32, 2-stage cp.async pipeline. smem stride 36 floats (bank-safe).
// M,N % 128 == 0, K % 32 == 0.
// ---------------------------------------------------------------------------
template <bool ROUND_OUT>
__global__ __launch_bounds__(256) void gemm_mma(
    const float* __restrict__ A,
    const float* __restrict__ Bm,
    const float* __restrict__ bias,
    float* __restrict__ C,
    int M, int N, int K)
{
    extern __shared__ float smem[];          // 2 stages x (A 128x36 + B 128x36)
    constexpr int TILE = 4608;               // 128*36 floats
    constexpr int STAGE = 2 * TILE;

    const int tid  = threadIdx.x;
    const int wid  = tid >> 5;
    const int lane = tid & 31;
    const int q    = lane >> 2;              // 0..7
    const int r    = lane & 3;               // 0..3
    const int wm   = (wid & 1) * 64;
    const int wn   = (wid >> 1) * 32;
    const int m0   = blockIdx.y * 128;
    const int n0   = blockIdx.x * 128;

    const uint32_t sb = smem_to_u32(smem);

    float acc[4][4][4];
    #pragma unroll
    for (int i = 0; i < 4; i++)
        #pragma unroll
        for (int j = 0; j < 4; j++)
            #pragma unroll
            for (int c = 0; c < 4; c++) acc[i][j][c] = 0.f;

    const int nK = K / 32;

    // stage loader: 1024 x 16B per tile, 256 threads -> 4 units each per tile
    auto load_chunk = [&](int kc, int stage) {
        const uint32_t aAddr = sb + stage * STAGE * 4;
        const uint32_t bAddr = aAddr + TILE * 4;
        const int k0 = kc * 32;
        #pragma unroll
        for (int i = 0; i < 4; i++) {
            int u  = i * 256 + tid;
            int rr = u >> 3;
            int c4 = u & 7;
            uint32_t off = (uint32_t)(rr * 36 + c4 * 4) * 4;
            cp16(aAddr + off, A  + (size_t)(m0 + rr) * K + k0 + c4 * 4);
            cp16(bAddr + off, Bm + (size_t)(n0 + rr) * K + k0 + c4 * 4);
        }
        asm volatile("cp.async.commit_group;" ::: "memory");
    };

    load_chunk(0, 0);

    for (int kc = 0; kc < nK; kc++) {
        const int stage = kc & 1;
        if (kc + 1 < nK) {
            load_chunk(kc + 1, stage ^ 1);
            asm volatile("cp.async.wait_group 1;" ::: "memory");
        } else {
            asm volatile("cp.async.wait_group 0;" ::: "memory");
        }
        __syncthreads();

        const float* Ab = smem + stage * STAGE;
        const float* Bb = Ab + TILE;

        #pragma unroll
        for (int ks = 0; ks < 4; ks++) {
            const int k = ks * 8;
            uint32_t a[4][4];
            #pragma unroll
            for (int i = 0; i < 4; i++) {
                const int m = wm + 16 * i + q;
                a[i][0] = __float_as_uint(Ab[m * 36 + k + r]);
                a[i][1] = __float_as_uint(Ab[(m + 8) * 36 + k + r]);
                a[i][2] = __float_as_uint(Ab[m * 36 + k + r + 4]);
                a[i][3] = __float_as_uint(Ab[(m + 8) * 36 + k + r + 4]);
            }
            uint32_t bfr[4][2];
            #pragma unroll
            for (int j = 0; j < 4; j++) {
                const int n = wn + 8 * j + q;
                bfr[j][0] = __float_as_uint(Bb[n * 36 + k + r]);
                bfr[j][1] = __float_as_uint(Bb[n * 36 + k + r + 4]);
            }
            #pragma unroll
            for (int i = 0; i < 4; i++)
                #pragma unroll
                for (int j = 0; j < 4; j++) {
                    asm volatile(
                        "mma.sync.aligned.m16n8k8.row.col.f32.tf32.tf32.f32 "
                        "{%0,%1,%2,%3}, {%4,%5,%6,%7}, {%8,%9}, {%0,%1,%2,%3};"
                        : "+f"(acc[i][j][0]), "+f"(acc[i][j][1]),
                          "+f"(acc[i][j][2]), "+f"(acc[i][j][3])
                        : "r"(a[i][0]), "r"(a[i][1]), "r"(a[i][2]), "r"(a[i][3]),
                          "r"(bfr[j][0]), "r"(bfr[j][1]));
                }
        }
        __syncthreads();
    }

    // epilogue
    #pragma unroll
    for (int i = 0; i < 4; i++) {
        #pragma unroll
        for (int j = 0; j < 4; j++) {
            const int row = m0 + wm + 16 * i + q;
            const int col = n0 + wn + 8 * j + 2 * r;
            const float bj0 = bias[col];
            const float bj1 = bias[col + 1];
            float v00 = fmaxf(acc[i][j][0] + bj0, 0.f);
            float v01 = fmaxf(acc[i][j][1] + bj1, 0.f);
            float v10 = fmaxf(acc[i][j][2] + bj0, 0.f);
            float v11 = fmaxf(acc[i][j][3] + bj1, 0.f);
            if (ROUND_OUT) {
                v00 = tf32r(v00); v01 = tf32r(v01);
                v10 = tf32r(v10); v11 = tf32r(v11);
            }
            float2 lo = make_float2(v00, v01);
            float2 hi = make_float2(v10, v11);
            *(float2*)(C + (size_t)row * N + col)       = lo;
            *(float2*)(C + (size_t)(row + 8) * N + col) = hi;
        }
    }
}

// ---------------------------------------------------------------------------
extern "C" void kernel_launch(void* const* d_in, const int* in_sizes, int n_in,
                              void* d_out, int out_size)
{
    const float* pov   = (const float*)d_in[0];
    const float* white = (const float*)d_in[1];
    const float* black = (const float*)d_in[2];
    const float* Ww    = (const float*)d_in[3];
    const float* bw    = (const float*)d_in[4];
    const float* Wb    = (const float*)d_in[5];
    const float* bb    = (const float*)d_in[6];
    const float* W0    = (const float*)d_in[7];
    const float* b0    = (const float*)d_in[8];
    const float* W1    = (const float*)d_in[9];
    const float* b1    = (const float*)d_in[10];
    const float* W2    = (const float*)d_in[11];
    const float* b2    = (const float*)d_in[12];
    const float* Wm0   = (const float*)d_in[13];
    const float* bm0   = (const float*)d_in[14];
    const float* Wm1   = (const float*)d_in[15];
    const float* bm1   = (const float*)d_in[16];

    const int B = in_sizes[0];
    float* out  = (float*)d_out;
    float* xout = out;                  // [B]
    float* aout = out + B;              // [B, MOVE_N]

    float *wwT_ptr, *wbT_ptr, *base_ptr, *hidden_ptr, *wm0r_ptr, *wm1r_ptr;
    cudaGetSymbolAddress((void**)&wwT_ptr,    g_WwT);
    cudaGetSymbolAddress((void**)&wbT_ptr,    g_WbT);
    cudaGetSymbolAddress((void**)&base_ptr,   g_base);
    cudaGetSymbolAddress((void**)&hidden_ptr, g_hidden);
    cudaGetSymbolAddress((void**)&wm0r_ptr,   g_Wm0r);
    cudaGetSymbolAddress((void**)&wm1r_ptr,   g_Wm1r);

    static bool attr_done = false;
    if (!attr_done) {
        cudaFuncSetAttribute(gemm_mma<true>,
            cudaFuncAttributeMaxDynamicSharedMemorySize, 73728);
        cudaFuncSetAttribute(gemm_mma<false>,
            cudaFuncAttributeMaxDynamicSharedMemorySize, 73728);
        attr_done = true;
    }

    // table transposes (tf32-rounded)
    {
        dim3 grid(HALF_KP / 32, 256 / 32);
        dim3 blk(32, 8);
        transpose_kernel<<<grid, blk>>>(Ww, wwT_ptr);
        transpose_kernel<<<grid, blk>>>(Wb, wbT_ptr);
    }
    // move-head weight rounding
    {
        int n4 = 256 * 512 / 4;
        round_kernel<<<(n4 + 255) / 256, 256>>>(Wm0, wm0r_ptr, n4);
        n4 = MOVE_N * 256 / 4;
        round_kernel<<<(n4 + 255) / 256, 256>>>(Wm1, wm1r_ptr, n4);
    }

    feat_kernel<<<B, 256>>>(pov, white, black, wwT_ptr, bw, wbT_ptr, bb,
                            W0, b0, W1, b1, W2, b2, xout);

    // hidden = tf32r(relu(base @ Wm0^T + bm0))   M=B, N=256, K=512
    {
        dim3 grid(256 / 128, B / 128);
        gemm_mma<true><<<grid, 256, 73728>>>(base_ptr, wm0r_ptr, bm0,
                                             hidden_ptr, B, 256, 512);
    }
    // a = relu(hidden @ Wm1^T + bm1)             M=B, N=4096, K=256
    {
        dim3 grid(MOVE_N / 128, B / 128);
        gemm_mma<false><<<grid, 256, 73728>>>(hidden_ptr, wm1r_ptr, bm1,
                                              aout, B, MOVE_N, 256);
    }
}

// round 6
// speedup vs baseline: 1.3218x; 1.0353x over previous
#include <cuda_runtime.h>
#include <cstdint>

// ---------------------------------------------------------------------------
// NNUE forward, TF32-faithful, target sm_100 (mma.sync tensor path).
//   memset:   zero per-position feature counters
//   transpose: Ww/Wb (256 x 40960) -> (40960 x 256), tf32-rounded (one launch)
//   round:    Wm0/Wm1 -> tf32-rounded scratch
//   scan:     grid-stride streaming scan of white/black multihot -> g_idx/g_cnt
//   gather:   per-position gather-sum + pov select + relu -> base[B,512];
//             fused value head (512->32->32->1)
//   gemm_mma: mma.sync m16n8k8 tf32, 128x128 CTA tile, cp.async 2-stage
//             hidden = tf32r(relu(base @ Wm0^T + bm0))   [B,256]
//             a      = relu(hidden @ Wm1^T + bm1)        [B,4096]
// ---------------------------------------------------------------------------

#define HALF_KP 40960
#define HALF_KP4 (HALF_KP / 4)
#define MOVE_N  4096
#define BATCH_MAX 4096

__device__ float g_WwT[(size_t)HALF_KP * 256];
__device__ float g_WbT[(size_t)HALF_KP * 256];
__device__ float g_base[BATCH_MAX * 512];
__device__ float g_hidden[BATCH_MAX * 256];
__device__ float g_Wm0r[256 * 512];
__device__ float g_Wm1r[(size_t)MOVE_N * 256];
__device__ int   g_cnt[2 * BATCH_MAX];
__device__ int   g_idx[2 * BATCH_MAX * 64];

__device__ __forceinline__ float tf32r(float x) {
    uint32_t u;
    asm("cvt.rna.tf32.f32 %0, %1;" : "=r"(u) : "f"(x));
    return __uint_as_float(u);
}

__device__ __forceinline__ uint32_t smem_to_u32(const void* p) {
    uint32_t a;
    asm("{ .reg .u64 t; cvta.to.shared.u64 t, %1; cvt.u32.u64 %0, t; }"
        : "=r"(a) : "l"(p));
    return a;
}

__device__ __forceinline__ void cp16(uint32_t dst, const void* src) {
    asm volatile("cp.async.cg.shared.global [%0], [%1], 16;"
                 :: "r"(dst), "l"(src) : "memory");
}

// ---------------------------------------------------------------------------
// Fused transpose of both tables: [256, HALF_KP] -> [HALF_KP, 256], tf32.
// ---------------------------------------------------------------------------
__global__ __launch_bounds__(256) void transpose_kernel(
    const float* __restrict__ srcW, float* __restrict__ dstW,
    const float* __restrict__ srcB, float* __restrict__ dstB)
{
    __shared__ float tile[32][33];
    const float* src = blockIdx.z ? srcB : srcW;
    float*       dst = blockIdx.z ? dstB : dstW;
    const int f0 = blockIdx.x * 32;
    const int o0 = blockIdx.y * 32;
    const int tx = threadIdx.x;
    const int ty = threadIdx.y;
    #pragma unroll
    for (int i = 0; i < 32; i += 8)
        tile[ty + i][tx] = tf32r(src[(size_t)(o0 + ty + i) * HALF_KP + f0 + tx]);
    __syncthreads();
    #pragma unroll
    for (int i = 0; i < 32; i += 8)
        dst[(size_t)(f0 + ty + i) * 256 + o0 + tx] = tile[tx][ty + i];
}

__global__ __launch_bounds__(256) void round_kernel(
    const float* __restrict__ src, float* __restrict__ dst, int n4)
{
    int i = blockIdx.x * 256 + threadIdx.x;
    if (i < n4) {
        float4 v = ((const float4*)src)[i];
        float4 w;
        w.x = tf32r(v.x); w.y = tf32r(v.y); w.z = tf32r(v.z); w.w = tf32r(v.w);
        ((float4*)dst)[i] = w;
    }
}

// ---------------------------------------------------------------------------
// Streaming scan: find nonzeros of white/black, append feature indices.
// Pure-bandwidth kernel; __ldcs to avoid polluting L2 (tables live there).
// ---------------------------------------------------------------------------
__device__ __forceinline__ void scan_one(
    const float4* __restrict__ white, const float4* __restrict__ black, int i)
{
    const float4 v = __ldcs(white + i);
    const float4 u = __ldcs(black + i);
    const int pos = i / HALF_KP4;
    const int f0  = (i - pos * HALF_KP4) * 4;
    if (v.x != 0.f) { int p = atomicAdd(&g_cnt[pos], 1); if (p < 64) g_idx[pos*64+p] = f0+0; }
    if (v.y != 0.f) { int p = atomicAdd(&g_cnt[pos], 1); if (p < 64) g_idx[pos*64+p] = f0+1; }
    if (v.z != 0.f) { int p = atomicAdd(&g_cnt[pos], 1); if (p < 64) g_idx[pos*64+p] = f0+2; }
    if (v.w != 0.f) { int p = atomicAdd(&g_cnt[pos], 1); if (p < 64) g_idx[pos*64+p] = f0+3; }
    const int posb = BATCH_MAX + pos;
    if (u.x != 0.f) { int p = atomicAdd(&g_cnt[posb], 1); if (p < 64) g_idx[posb*64+p] = f0+0; }
    if (u.y != 0.f) { int p = atomicAdd(&g_cnt[posb], 1); if (p < 64) g_idx[posb*64+p] = f0+1; }
    if (u.z != 0.f) { int p = atomicAdd(&g_cnt[posb], 1); if (p < 64) g_idx[posb*64+p] = f0+2; }
    if (u.w != 0.f) { int p = atomicAdd(&g_cnt[posb], 1); if (p < 64) g_idx[posb*64+p] = f0+3; }
}

__global__ __launch_bounds__(256) void scan_kernel(
    const float4* __restrict__ white, const float4* __restrict__ black,
    int total4)
{
    const int stride = gridDim.x * 256;
    int i = blockIdx.x * 256 + threadIdx.x;
    for (; i + stride < total4; i += 2 * stride) {
        scan_one(white, black, i);
        scan_one(white, black, i + stride);
    }
    if (i < total4) scan_one(white, black, i);
}

// ---------------------------------------------------------------------------
// Gather-sum + pov select + value head. One block per position.
// ---------------------------------------------------------------------------
__global__ __launch_bounds__(256) void gather_kernel(
    const float* __restrict__ pov,
    const float* __restrict__ WwT, const float* __restrict__ bw,
    const float* __restrict__ WbT, const float* __restrict__ bb,
    const float* __restrict__ W0, const float* __restrict__ b0,
    const float* __restrict__ W1, const float* __restrict__ b1,
    const float* __restrict__ W2, const float* __restrict__ b2,
    float* __restrict__ xout)
{
    const int b = blockIdx.x;
    const int t = threadIdx.x;

    __shared__ int   sIdxW[64], sIdxB[64];
    __shared__ float sbase[512];
    __shared__ float h0[32], h1[32];
    __shared__ int   snW, snB;

    if (t == 0) {
        snW = min(g_cnt[b], 64);
        snB = min(g_cnt[BATCH_MAX + b], 64);
    }
    if (t < 64)                sIdxW[t]      = g_idx[b * 64 + t];
    else if (t < 128)          sIdxB[t - 64] = g_idx[(BATCH_MAX + b) * 64 + t - 64];
    __syncthreads();

    const int nW = snW;
    const int nB = snB;

    float accw = 0.f;
    for (int i = 0; i < nW; i++) accw += WwT[(size_t)sIdxW[i] * 256 + t];
    accw += bw[t];
    float accb = 0.f;
    for (int i = 0; i < nB; i++) accb += WbT[(size_t)sIdxB[i] * 256 + t];
    accb += bb[t];

    const bool p = (pov[b] != 0.f);
    const float r0 = tf32r(fmaxf(p ? accw : accb, 0.f));
    const float r1 = tf32r(fmaxf(p ? accb : accw, 0.f));
    sbase[t]       = r0;
    sbase[t + 256] = r1;
    float* baserow = g_base + (size_t)b * 512;
    baserow[t]       = r0;
    baserow[t + 256] = r1;
    __syncthreads();

    if (t < 32) {
        float s0 = 0.f, s1 = 0.f, s2 = 0.f, s3 = 0.f;
        const float* w = W0 + t * 512;
        #pragma unroll 4
        for (int k = 0; k < 512; k += 4) {
            s0 += tf32r(w[k+0]) * sbase[k+0];
            s1 += tf32r(w[k+1]) * sbase[k+1];
            s2 += tf32r(w[k+2]) * sbase[k+2];
            s3 += tf32r(w[k+3]) * sbase[k+3];
        }
        h0[t] = fmaxf(((s0 + s1) + (s2 + s3)) + b0[t], 0.f);
    }
    __syncthreads();
    if (t < 32) {
        float s = 0.f;
        const float* w = W1 + t * 32;
        #pragma unroll
        for (int k = 0; k < 32; k++) s += tf32r(w[k]) * tf32r(h0[k]);
        h1[t] = fmaxf(s + b1[t], 0.f);
    }
    __syncthreads();
    if (t == 0) {
        float s = 0.f;
        #pragma unroll
        for (int k = 0; k < 32; k++) s += tf32r(W2[k]) * tf32r(h1[k]);
        xout[b] = s + b2[0];
    }
}

// ---------------------------------------------------------------------------
// TF32 mma.sync NT GEMM: C[M,N] = relu(A[M,K] @ Bm[N,K]^T + bias[N])
// A, Bm already tf32-rounded in gmem. 128x128 CTA tile, 8 warps, warp 64x32.
// K-chunk 32, 2-stage cp.async pipeline. smem stride 36 floats (bank-safe).
// ---------------------------------------------------------------------------
template <bool ROUND_OUT>
__global__ __launch_bounds__(256) void gemm_mma(
    const float* __restrict__ A,
    const float* __restrict__ Bm,
    const float* __restrict__ bias,
    float* __restrict__ C,
    int M, int N, int K)
{
    extern __shared__ float smem[];          // 2 stages x (A 128x36 + B 128x36)
    constexpr int TILE = 4608;               // 128*36 floats
    constexpr int STAGE = 2 * TILE;

    const int tid  = threadIdx.x;
    const int wid  = tid >> 5;
    const int lane = tid & 31;
    const int q    = lane >> 2;
    const int r    = lane & 3;
    const int wm   = (wid & 1) * 64;
    const int wn   = (wid >> 1) * 32;
    const int m0   = blockIdx.y * 128;
    const int n0   = blockIdx.x * 128;

    const uint32_t sb = smem_to_u32(smem);

    float acc[4][4][4];
    #pragma unroll
    for (int i = 0; i < 4; i++)
        #pragma unroll
        for (int j = 0; j < 4; j++)
            #pragma unroll
            for (int c = 0; c < 4; c++) acc[i][j][c] = 0.f;

    const int nK = K / 32;

    auto load_chunk = [&](int kc, int stage) {
        const uint32_t aAddr = sb + stage * STAGE * 4;
        const uint32_t bAddr = aAddr + TILE * 4;
        const int k0 = kc * 32;
        #pragma unroll
        for (int i = 0; i < 4; i++) {
            int u  = i * 256 + tid;
            int rr = u >> 3;
            int c4 = u & 7;
            uint32_t off = (uint32_t)(rr * 36 + c4 * 4) * 4;
            cp16(aAddr + off, A  + (size_t)(m0 + rr) * K + k0 + c4 * 4);
            cp16(bAddr + off, Bm + (size_t)(n0 + rr) * K + k0 + c4 * 4);
        }
        asm volatile("cp.async.commit_group;" ::: "memory");
    };

    load_chunk(0, 0);

    for (int kc = 0; kc < nK; kc++) {
        const int stage = kc & 1;
        if (kc + 1 < nK) {
            load_chunk(kc + 1, stage ^ 1);
            asm volatile("cp.async.wait_group 1;" ::: "memory");
        } else {
            asm volatile("cp.async.wait_group 0;" ::: "memory");
        }
        __syncthreads();

        const float* Ab = smem + stage * STAGE;
        const float* Bb = Ab + TILE;

        #pragma unroll
        for (int ks = 0; ks < 4; ks++) {
            const int k = ks * 8;
            uint32_t a[4][4];
            #pragma unroll
            for (int i = 0; i < 4; i++) {
                const int m = wm + 16 * i + q;
                a[i][0] = __float_as_uint(Ab[m * 36 + k + r]);
                a[i][1] = __float_as_uint(Ab[(m + 8) * 36 + k + r]);
                a[i][2] = __float_as_uint(Ab[m * 36 + k + r + 4]);
                a[i][3] = __float_as_uint(Ab[(m + 8) * 36 + k + r + 4]);
            }
            uint32_t bfr[4][2];
            #pragma unroll
            for (int j = 0; j < 4; j++) {
                const int n = wn + 8 * j + q;
                bfr[j][0] = __float_as_uint(Bb[n * 36 + k + r]);
                bfr[j][1] = __float_as_uint(Bb[n * 36 + k + r + 4]);
            }
            #pragma unroll
            for (int i = 0; i < 4; i++)
                #pragma unroll
                for (int j = 0; j < 4; j++) {
                    asm volatile(
                        "mma.sync.aligned.m16n8k8.row.col.f32.tf32.tf32.f32 "
                        "{%0,%1,%2,%3}, {%4,%5,%6,%7}, {%8,%9}, {%0,%1,%2,%3};"
                        : "+f"(acc[i][j][0]), "+f"(acc[i][j][1]),
                          "+f"(acc[i][j][2]), "+f"(acc[i][j][3])
                        : "r"(a[i][0]), "r"(a[i][1]), "r"(a[i][2]), "r"(a[i][3]),
                          "r"(bfr[j][0]), "r"(bfr[j][1]));
                }
        }
        __syncthreads();
    }

    #pragma unroll
    for (int i = 0; i < 4; i++) {
        #pragma unroll
        for (int j = 0; j < 4; j++) {
            const int row = m0 + wm + 16 * i + q;
            const int col = n0 + wn + 8 * j + 2 * r;
            const float bj0 = bias[col];
            const float bj1 = bias[col + 1];
            float v00 = fmaxf(acc[i][j][0] + bj0, 0.f);
            float v01 = fmaxf(acc[i][j][1] + bj1, 0.f);
            float v10 = fmaxf(acc[i][j][2] + bj0, 0.f);
            float v11 = fmaxf(acc[i][j][3] + bj1, 0.f);
            if (ROUND_OUT) {
                v00 = tf32r(v00); v01 = tf32r(v01);
                v10 = tf32r(v10); v11 = tf32r(v11);
            }
            float2 lo = make_float2(v00, v01);
            float2 hi = make_float2(v10, v11);
            *(float2*)(C + (size_t)row * N + col)       = lo;
            *(float2*)(C + (size_t)(row + 8) * N + col) = hi;
        }
    }
}

// ---------------------------------------------------------------------------
extern "C" void kernel_launch(void* const* d_in, const int* in_sizes, int n_in,
                              void* d_out, int out_size)
{
    const float* pov   = (const float*)d_in[0];
    const float* white = (const float*)d_in[1];
    const float* black = (const float*)d_in[2];
    const float* Ww    = (const float*)d_in[3];
    const float* bw    = (const float*)d_in[4];
    const float* Wb    = (const float*)d_in[5];
    const float* bb    = (const float*)d_in[6];
    const float* W0    = (const float*)d_in[7];
    const float* b0    = (const float*)d_in[8];
    const float* W1    = (const float*)d_in[9];
    const float* b1    = (const float*)d_in[10];
    const float* W2    = (const float*)d_in[11];
    const float* b2    = (const float*)d_in[12];
    const float* Wm0   = (const float*)d_in[13];
    const float* bm0   = (const float*)d_in[14];
    const float* Wm1   = (const float*)d_in[15];
    const float* bm1   = (const float*)d_in[16];

    const int B = in_sizes[0];
    float* out  = (float*)d_out;
    float* xout = out;                  // [B]
    float* aout = out + B;              // [B, MOVE_N]

    float *wwT_ptr, *wbT_ptr, *base_ptr, *hidden_ptr, *wm0r_ptr, *wm1r_ptr;
    int* cnt_ptr;
    cudaGetSymbolAddress((void**)&wwT_ptr,    g_WwT);
    cudaGetSymbolAddress((void**)&wbT_ptr,    g_WbT);
    cudaGetSymbolAddress((void**)&base_ptr,   g_base);
    cudaGetSymbolAddress((void**)&hidden_ptr, g_hidden);
    cudaGetSymbolAddress((void**)&wm0r_ptr,   g_Wm0r);
    cudaGetSymbolAddress((void**)&wm1r_ptr,   g_Wm1r);
    cudaGetSymbolAddress((void**)&cnt_ptr,    g_cnt);

    static bool attr_done = false;
    if (!attr_done) {
        cudaFuncSetAttribute(gemm_mma<true>,
            cudaFuncAttributeMaxDynamicSharedMemorySize, 73728);
        cudaFuncSetAttribute(gemm_mma<false>,
            cudaFuncAttributeMaxDynamicSharedMemorySize, 73728);
        attr_done = true;
    }

    // zero per-position counters (graph-capturable memset node)
    cudaMemsetAsync(cnt_ptr, 0, 2 * BATCH_MAX * sizeof(int));

    // streaming index extraction (independent of table transposes)
    {
        const int total4 = B * HALF_KP4;
        scan_kernel<<<2048, 256>>>((const float4*)white, (const float4*)black,
                                   total4);
    }

    // table transposes (tf32-rounded), both in one launch
    {
        dim3 grid(HALF_KP / 32, 256 / 32, 2);
        dim3 blk(32, 8);
        transpose_kernel<<<grid, blk>>>(Ww, wwT_ptr, Wb, wbT_ptr);
    }

    // move-head weight rounding
    {
        int n4 = 256 * 512 / 4;
        round_kernel<<<(n4 + 255) / 256, 256>>>(Wm0, wm0r_ptr, n4);
        n4 = MOVE_N * 256 / 4;
        round_kernel<<<(n4 + 255) / 256, 256>>>(Wm1, wm1r_ptr, n4);
    }

    // gather + pov select + value head
    gather_kernel<<<B, 256>>>(pov, wwT_ptr, bw, wbT_ptr, bb,
                              W0, b0, W1, b1, W2, b2, xout);

    // hidden = tf32r(relu(base @ Wm0^T + bm0))   M=B, N=256, K=512
    {
        dim3 grid(256 / 128, B / 128);
        gemm_mma<true><<<grid, 256, 73728>>>(base_ptr, wm0r_ptr, bm0,
                                             hidden_ptr, B, 256, 512);
    }
    // a = relu(hidden @ Wm1^T + bm1)             M=B, N=4096, K=256
    {
        dim3 grid(MOVE_N / 128, B / 128);
        gemm_mma<false><<<grid, 256, 73728>>>(hidden_ptr, wm1r_ptr, bm1,
                                              aout, B, MOVE_N, 256);
    }
}

// round 7
// speedup vs baseline: 1.6352x; 1.2371x over previous
#include <cuda_runtime.h>
#include <cstdint>

// ---------------------------------------------------------------------------
// NNUE forward, TF32-faithful, target sm_100 (mma.sync tensor path).
//   memset:    zero per-position feature counters
//   round:     Wm0/Wm1/W0/W1/W2 -> tf32-rounded scratch
//   transpose: Ww/Wb (256 x 40960) -> (40960 x 256), tf32-rounded (one launch)
//   scan:      OR-accumulate register-resident scan of white/black multihot
//              -> g_idx/g_cnt   (instruction-minimized, ~0.23 instr/B)
//   gather:    per-position gather-sum + pov select + relu -> base[B,512];
//              fused value head (512->32->32->1, fc0 8-way parallel)
//   gemm_mma:  mma.sync m16n8k8 tf32, 128x128 CTA tile, cp.async 2-stage
//              hidden = tf32r(relu(base @ Wm0^T + bm0))   [B,256]
//              a      = relu(hidden @ Wm1^T + bm1)        [B,4096]
// ---------------------------------------------------------------------------

#define HALF_KP 40960
#define HALF_KP4 (HALF_KP / 4)
#define MOVE_N  4096
#define BATCH_MAX 4096

__device__ float g_WwT[(size_t)HALF_KP * 256];
__device__ float g_WbT[(size_t)HALF_KP * 256];
__device__ float g_base[BATCH_MAX * 512];
__device__ float g_hidden[BATCH_MAX * 256];
__device__ float g_Wm0r[256 * 512];
__device__ float g_Wm1r[(size_t)MOVE_N * 256];
__device__ float g_W0r[32 * 512];
__device__ float g_W1r[32 * 32];
__device__ float g_W2r[32];
__device__ int   g_cnt[2 * BATCH_MAX];
__device__ int   g_idx[2 * BATCH_MAX * 64];

__device__ __forceinline__ float tf32r(float x) {
    uint32_t u;
    asm("cvt.rna.tf32.f32 %0, %1;" : "=r"(u) : "f"(x));
    return __uint_as_float(u);
}

__device__ __forceinline__ uint32_t smem_to_u32(const void* p) {
    uint32_t a;
    asm("{ .reg .u64 t; cvta.to.shared.u64 t, %1; cvt.u32.u64 %0, t; }"
        : "=r"(a) : "l"(p));
    return a;
}

__device__ __forceinline__ void cp16(uint32_t dst, const void* src) {
    asm volatile("cp.async.cg.shared.global [%0], [%1], 16;"
                 :: "r"(dst), "l"(src) : "memory");
}

// ---------------------------------------------------------------------------
__global__ __launch_bounds__(256) void round_kernel(
    const float* __restrict__ src, float* __restrict__ dst, int n4)
{
    int i = blockIdx.x * 256 + threadIdx.x;
    if (i < n4) {
        float4 v = ((const float4*)src)[i];
        float4 w;
        w.x = tf32r(v.x); w.y = tf32r(v.y); w.z = tf32r(v.z); w.w = tf32r(v.w);
        ((float4*)dst)[i] = w;
    }
}

// rounds W0 (16384), W1 (1024), W2 (32) in one launch
__global__ __launch_bounds__(256) void round_heads_kernel(
    const float* __restrict__ W0, float* __restrict__ W0r,
    const float* __restrict__ W1, float* __restrict__ W1r,
    const float* __restrict__ W2, float* __restrict__ W2r)
{
    int i = blockIdx.x * 256 + threadIdx.x;
    if (i < 16384)       W0r[i] = tf32r(W0[i]);
    else if (i < 17408)  W1r[i - 16384] = tf32r(W1[i - 16384]);
    else if (i < 17440)  W2r[i - 17408] = tf32r(W2[i - 17408]);
}

// ---------------------------------------------------------------------------
// Fused transpose of both tables: [256, HALF_KP] -> [HALF_KP, 256], tf32.
// ---------------------------------------------------------------------------
__global__ __launch_bounds__(256) void transpose_kernel(
    const float* __restrict__ srcW, float* __restrict__ dstW,
    const float* __restrict__ srcB, float* __restrict__ dstB)
{
    __shared__ float tile[32][33];
    const float* src = blockIdx.z ? srcB : srcW;
    float*       dst = blockIdx.z ? dstB : dstW;
    const int f0 = blockIdx.x * 32;
    const int o0 = blockIdx.y * 32;
    const int tx = threadIdx.x;
    const int ty = threadIdx.y;
    #pragma unroll
    for (int i = 0; i < 32; i += 8)
        tile[ty + i][tx] = tf32r(src[(size_t)(o0 + ty + i) * HALF_KP + f0 + tx]);
    __syncthreads();
    #pragma unroll
    for (int i = 0; i < 32; i += 8)
        dst[(size_t)(f0 + ty + i) * 256 + o0 + tx] = tile[tx][ty + i];
}

// ---------------------------------------------------------------------------
// Scan: warp-cooperative 4KB chunks, register-resident OR-accumulate test.
// One warp chunk = 256 consecutive float4 (never straddles a position row,
// since HALF_KP4 % 256 == 0). Rare path re-walks registers, not memory.
// ---------------------------------------------------------------------------
__device__ __forceinline__ void scan_chunk(
    const uint4* __restrict__ arr, int base, int lane, int side)
{
    uint4 v[8];
    #pragma unroll
    for (int k = 0; k < 8; k++)
        v[k] = __ldcs(arr + base + k * 32 + lane);
    uint32_t a0 = 0, a1 = 0;
    #pragma unroll
    for (int k = 0; k < 8; k++) {
        a0 |= v[k].x | v[k].y;        // LOP3
        a1 |= v[k].z | v[k].w;        // LOP3
    }
    if (a0 | a1) {
        const int pos   = base / HALF_KP4;
        const int fbase = (base - pos * HALF_KP4) * 4;
        int* cnt = &g_cnt[side + pos];
        int* idx = &g_idx[(size_t)(side + pos) * 64];
        #pragma unroll
        for (int k = 0; k < 8; k++) {
            if (v[k].x | v[k].y | v[k].z | v[k].w) {
                const int f0 = fbase + (k * 32 + lane) * 4;
                if (v[k].x) { int p = atomicAdd(cnt, 1); if (p < 64) idx[p] = f0;     }
                if (v[k].y) { int p = atomicAdd(cnt, 1); if (p < 64) idx[p] = f0 + 1; }
                if (v[k].z) { int p = atomicAdd(cnt, 1); if (p < 64) idx[p] = f0 + 2; }
                if (v[k].w) { int p = atomicAdd(cnt, 1); if (p < 64) idx[p] = f0 + 3; }
            }
        }
    }
}

__global__ __launch_bounds__(256) void scan_kernel(
    const uint4* __restrict__ white, const uint4* __restrict__ black,
    int nchunks)
{
    const int lane  = threadIdx.x & 31;
    const int warp0 = blockIdx.x * 8 + (threadIdx.x >> 5);
    const int nwarp = gridDim.x * 8;
    for (int c = warp0; c < nchunks; c += nwarp) {
        const int base = c * 256;
        scan_chunk(white, base, lane, 0);
        scan_chunk(black, base, lane, BATCH_MAX);
    }
}

// ---------------------------------------------------------------------------
// Gather-sum + pov select + value head. One block per position.
// ---------------------------------------------------------------------------
__global__ __launch_bounds__(256) void gather_kernel(
    const float* __restrict__ pov,
    const float* __restrict__ WwT, const float* __restrict__ bw,
    const float* __restrict__ WbT, const float* __restrict__ bb,
    const float* __restrict__ W0r, const float* __restrict__ b0,
    const float* __restrict__ W1r, const float* __restrict__ b1,
    const float* __restrict__ W2r, const float* __restrict__ b2,
    float* __restrict__ xout)
{
    const int b = blockIdx.x;
    const int t = threadIdx.x;

    __shared__ int   sIdxW[64], sIdxB[64];
    __shared__ float sbase[512];
    __shared__ float h0[32], h1[32];
    __shared__ int   snW, snB;

    if (t == 0) {
        snW = min(g_cnt[b], 64);
        snB = min(g_cnt[BATCH_MAX + b], 64);
    }
    if (t < 64)       sIdxW[t]      = g_idx[b * 64 + t];
    else if (t < 128) sIdxB[t - 64] = g_idx[(size_t)(BATCH_MAX + b) * 64 + t - 64];
    __syncthreads();

    const int nW = snW;
    const int nB = snB;

    float accw = 0.f;
    for (int i = 0; i < nW; i++) accw += WwT[(size_t)sIdxW[i] * 256 + t];
    accw += bw[t];
    float accb = 0.f;
    for (int i = 0; i < nB; i++) accb += WbT[(size_t)sIdxB[i] * 256 + t];
    accb += bb[t];

    const bool p = (pov[b] != 0.f);
    const float r0 = tf32r(fmaxf(p ? accw : accb, 0.f));
    const float r1 = tf32r(fmaxf(p ? accb : accw, 0.f));
    sbase[t]       = r0;
    sbase[t + 256] = r1;
    float* baserow = g_base + (size_t)b * 512;
    baserow[t]       = r0;
    baserow[t + 256] = r1;
    __syncthreads();

    // fc0: 32 outputs x 8 lanes each, shuffle-reduce within 8-lane groups
    {
        const int o = t >> 3;            // 0..31
        const int r = t & 7;             // 0..7
        const float4* w4 = (const float4*)(W0r + o * 512 + r * 64);
        const float4* s4 = (const float4*)(sbase + r * 64);
        float s0 = 0.f, s1 = 0.f, s2 = 0.f, s3 = 0.f;
        #pragma unroll
        for (int j = 0; j < 16; j++) {
            float4 wv = w4[j];
            float4 sv = s4[j];
            s0 += wv.x * sv.x; s1 += wv.y * sv.y;
            s2 += wv.z * sv.z; s3 += wv.w * sv.w;
        }
        float s = (s0 + s1) + (s2 + s3);
        s += __shfl_down_sync(0xffffffffu, s, 4);
        s += __shfl_down_sync(0xffffffffu, s, 2);
        s += __shfl_down_sync(0xffffffffu, s, 1);
        if (r == 0) h0[o] = tf32r(fmaxf(s + b0[o], 0.f));
    }
    __syncthreads();
    if (t < 32) {
        float s = 0.f;
        const float* w = W1r + t * 32;
        #pragma unroll
        for (int k = 0; k < 32; k++) s += w[k] * h0[k];
        h1[t] = tf32r(fmaxf(s + b1[t], 0.f));
    }
    __syncthreads();
    if (t == 0) {
        float s = 0.f;
        #pragma unroll
        for (int k = 0; k < 32; k++) s += W2r[k] * h1[k];
        xout[b] = s + b2[0];
    }
}

// ---------------------------------------------------------------------------
// TF32 mma.sync NT GEMM: C[M,N] = relu(A[M,K] @ Bm[N,K]^T + bias[N])
// A, Bm already tf32-rounded in gmem. 128x128 CTA tile, 8 warps, warp 64x32.
// K-chunk 32, 2-stage cp.async pipeline. smem stride 36 floats (bank-safe).
// ---------------------------------------------------------------------------
template <bool ROUND_OUT>
__global__ __launch_bounds__(256) void gemm_mma(
    const float* __restrict__ A,
    const float* __restrict__ Bm,
    const float* __restrict__ bias,
    float* __restrict__ C,
    int M, int N, int K)
{
    extern __shared__ float smem[];          // 2 stages x (A 128x36 + B 128x36)
    constexpr int TILE = 4608;               // 128*36 floats
    constexpr int STAGE = 2 * TILE;

    const int tid  = threadIdx.x;
    const int wid  = tid >> 5;
    const int lane = tid & 31;
    const int q    = lane >> 2;
    const int r    = lane & 3;
    const int wm   = (wid & 1) * 64;
    const int wn   = (wid >> 1) * 32;
    const int m0   = blockIdx.y * 128;
    const int n0   = blockIdx.x * 128;

    const uint32_t sb = smem_to_u32(smem);

    float acc[4][4][4];
    #pragma unroll
    for (int i = 0; i < 4; i++)
        #pragma unroll
        for (int j = 0; j < 4; j++)
            #pragma unroll
            for (int c = 0; c < 4; c++) acc[i][j][c] = 0.f;

    const int nK = K / 32;

    auto load_chunk = [&](int kc, int stage) {
        const uint32_t aAddr = sb + stage * STAGE * 4;
        const uint32_t bAddr = aAddr + TILE * 4;
        const int k0 = kc * 32;
        #pragma unroll
        for (int i = 0; i < 4; i++) {
            int u  = i * 256 + tid;
            int rr = u >> 3;
            int c4 = u & 7;
            uint32_t off = (uint32_t)(rr * 36 + c4 * 4) * 4;
            cp16(aAddr + off, A  + (size_t)(m0 + rr) * K + k0 + c4 * 4);
            cp16(bAddr + off, Bm + (size_t)(n0 + rr) * K + k0 + c4 * 4);
        }
        asm volatile("cp.async.commit_group;" ::: "memory");
    };

    load_chunk(0, 0);

    for (int kc = 0; kc < nK; kc++) {
        const int stage = kc & 1;
        if (kc + 1 < nK) {
            load_chunk(kc + 1, stage ^ 1);
            asm volatile("cp.async.wait_group 1;" ::: "memory");
        } else {
            asm volatile("cp.async.wait_group 0;" ::: "memory");
        }
        __syncthreads();

        const float* Ab = smem + stage * STAGE;
        const float* Bb = Ab + TILE;

        #pragma unroll
        for (int ks = 0; ks < 4; ks++) {
            const int k = ks * 8;
            uint32_t a[4][4];
            #pragma unroll
            for (int i = 0; i < 4; i++) {
                const int m = wm + 16 * i + q;
                a[i][0] = __float_as_uint(Ab[m * 36 + k + r]);
                a[i][1] = __float_as_uint(Ab[(m + 8) * 36 + k + r]);
                a[i][2] = __float_as_uint(Ab[m * 36 + k + r + 4]);
                a[i][3] = __float_as_uint(Ab[(m + 8) * 36 + k + r + 4]);
            }
            uint32_t bfr[4][2];
            #pragma unroll
            for (int j = 0; j < 4; j++) {
                const int n = wn + 8 * j + q;
                bfr[j][0] = __float_as_uint(Bb[n * 36 + k + r]);
                bfr[j][1] = __float_as_uint(Bb[n * 36 + k + r + 4]);
            }
            #pragma unroll
            for (int i = 0; i < 4; i++)
                #pragma unroll
                for (int j = 0; j < 4; j++) {
                    asm volatile(
                        "mma.sync.aligned.m16n8k8.row.col.f32.tf32.tf32.f32 "
                        "{%0,%1,%2,%3}, {%4,%5,%6,%7}, {%8,%9}, {%0,%1,%2,%3};"
                        : "+f"(acc[i][j][0]), "+f"(acc[i][j][1]),
                          "+f"(acc[i][j][2]), "+f"(acc[i][j][3])
                        : "r"(a[i][0]), "r"(a[i][1]), "r"(a[i][2]), "r"(a[i][3]),
                          "r"(bfr[j][0]), "r"(bfr[j][1]));
                }
        }
        __syncthreads();
    }

    #pragma unroll
    for (int i = 0; i < 4; i++) {
        #pragma unroll
        for (int j = 0; j < 4; j++) {
            const int row = m0 + wm + 16 * i + q;
            const int col = n0 + wn + 8 * j + 2 * r;
            const float bj0 = bias[col];
            const float bj1 = bias[col + 1];
            float v00 = fmaxf(acc[i][j][0] + bj0, 0.f);
            float v01 = fmaxf(acc[i][j][1] + bj1, 0.f);
            float v10 = fmaxf(acc[i][j][2] + bj0, 0.f);
            float v11 = fmaxf(acc[i][j][3] + bj1, 0.f);
            if (ROUND_OUT) {
                v00 = tf32r(v00); v01 = tf32r(v01);
                v10 = tf32r(v10); v11 = tf32r(v11);
            }
            float2 lo = make_float2(v00, v01);
            float2 hi = make_float2(v10, v11);
            *(float2*)(C + (size_t)row * N + col)       = lo;
            *(float2*)(C + (size_t)(row + 8) * N + col) = hi;
        }
    }
}

// ---------------------------------------------------------------------------
extern "C" void kernel_launch(void* const* d_in, const int* in_sizes, int n_in,
                              void* d_out, int out_size)
{
    const float* pov   = (const float*)d_in[0];
    const float* white = (const float*)d_in[1];
    const float* black = (const float*)d_in[2];
    const float* Ww    = (const float*)d_in[3];
    const float* bw    = (const float*)d_in[4];
    const float* Wb    = (const float*)d_in[5];
    const float* bb    = (const float*)d_in[6];
    const float* W0    = (const float*)d_in[7];
    const float* b0    = (const float*)d_in[8];
    const float* W1    = (const float*)d_in[9];
    const float* b1    = (const float*)d_in[10];
    const float* W2    = (const float*)d_in[11];
    const float* b2    = (const float*)d_in[12];
    const float* Wm0   = (const float*)d_in[13];
    const float* bm0   = (const float*)d_in[14];
    const float* Wm1   = (const float*)d_in[15];
    const float* bm1   = (const float*)d_in[16];

    const int B = in_sizes[0];
    float* out  = (float*)d_out;
    float* xout = out;                  // [B]
    float* aout = out + B;              // [B, MOVE_N]

    float *wwT_ptr, *wbT_ptr, *base_ptr, *hidden_ptr;
    float *wm0r_ptr, *wm1r_ptr, *w0r_ptr, *w1r_ptr, *w2r_ptr;
    int* cnt_ptr;
    cudaGetSymbolAddress((void**)&wwT_ptr,    g_WwT);
    cudaGetSymbolAddress((void**)&wbT_ptr,    g_WbT);
    cudaGetSymbolAddress((void**)&base_ptr,   g_base);
    cudaGetSymbolAddress((void**)&hidden_ptr, g_hidden);
    cudaGetSymbolAddress((void**)&wm0r_ptr,   g_Wm0r);
    cudaGetSymbolAddress((void**)&wm1r_ptr,   g_Wm1r);
    cudaGetSymbolAddress((void**)&w0r_ptr,    g_W0r);
    cudaGetSymbolAddress((void**)&w1r_ptr,    g_W1r);
    cudaGetSymbolAddress((void**)&w2r_ptr,    g_W2r);
    cudaGetSymbolAddress((void**)&cnt_ptr,    g_cnt);

    static bool attr_done = false;
    if (!attr_done) {
        cudaFuncSetAttribute(gemm_mma<true>,
            cudaFuncAttributeMaxDynamicSharedMemorySize, 73728);
        cudaFuncSetAttribute(gemm_mma<false>,
            cudaFuncAttributeMaxDynamicSharedMemorySize, 73728);
        attr_done = true;
    }

    // zero per-position counters (graph-capturable memset node)
    cudaMemsetAsync(cnt_ptr, 0, 2 * BATCH_MAX * sizeof(int));

    // move-head + value-head weight rounding
    {
        int n4 = 256 * 512 / 4;
        round_kernel<<<(n4 + 255) / 256, 256>>>(Wm0, wm0r_ptr, n4);
        n4 = MOVE_N * 256 / 4;
        round_kernel<<<(n4 + 255) / 256, 256>>>(Wm1, wm1r_ptr, n4);
        round_heads_kernel<<<(17440 + 255) / 256, 256>>>(
            W0, w0r_ptr, W1, w1r_ptr, W2, w2r_ptr);
    }

    // table transposes (tf32-rounded), both in one launch
    {
        dim3 grid(HALF_KP / 32, 256 / 32, 2);
        dim3 blk(32, 8);
        transpose_kernel<<<grid, blk>>>(Ww, wwT_ptr, Wb, wbT_ptr);
    }

    // streaming index extraction
    {
        const int nchunks = B * HALF_KP4 / 256;   // 4KB warp chunks
        scan_kernel<<<896, 256>>>((const uint4*)white, (const uint4*)black,
                                  nchunks);
    }

    // gather + pov select + value head
    gather_kernel<<<B, 256>>>(pov, wwT_ptr, bw, wbT_ptr, bb,
                              w0r_ptr, b0, w1r_ptr, b1, w2r_ptr, b2, xout);

    // hidden = tf32r(relu(base @ Wm0^T + bm0))   M=B, N=256, K=512
    {
        dim3 grid(256 / 128, B / 128);
        gemm_mma<true><<<grid, 256, 73728>>>(base_ptr, wm0r_ptr, bm0,
                                             hidden_ptr, B, 256, 512);
    }
    // a = relu(hidden @ Wm1^T + bm1)             M=B, N=4096, K=256
    {
        dim3 grid(MOVE_N / 128, B / 128);
        gemm_mma<false><<<grid, 256, 73728>>>(hidden_ptr, wm1r_ptr, bm1,
                                              aout, B, MOVE_N, 256);
    }
}